// round 4
// baseline (speedup 1.0000x reference)
#include <cuda_runtime.h>
#include <cuda_fp16.h>
#include <cstdint>

#define D      128
#define LDH    136            // half row stride in smem (8-half pad -> 4-bank skew)
#define GEMM_T 256            // threads per GEMM CTA (8 warps)

// fp16 scratch tables (allocation-free __device__ globals)
__device__ __half g_Ktab[50000 * D];   // tanh((attr + item) @ Wk^T + bk)
__device__ __half g_A   [50000 * D];   // item @ Wv^T
__device__ __half g_B   [ 5000 * D];   // opin @ Wv^T + bv
__device__ __half g_Q   [10000 * D];   // tanh(user @ Wq^T + bq)

static __device__ __forceinline__ uint32_t smem_u32(const void* p) {
    return (uint32_t)__cvta_generic_to_shared(p);
}

static __device__ __forceinline__ void ldsm_x4(uint32_t& r0, uint32_t& r1,
                                               uint32_t& r2, uint32_t& r3, uint32_t addr) {
    asm volatile("ldmatrix.sync.aligned.m8n8.x4.shared.b16 {%0,%1,%2,%3}, [%4];"
                 : "=r"(r0), "=r"(r1), "=r"(r2), "=r"(r3) : "r"(addr));
}
static __device__ __forceinline__ void ldsm_x2(uint32_t& r0, uint32_t& r1, uint32_t addr) {
    asm volatile("ldmatrix.sync.aligned.m8n8.x2.shared.b16 {%0,%1}, [%2];"
                 : "=r"(r0), "=r"(r1) : "r"(addr));
}
static __device__ __forceinline__ void mma16816(float& d0, float& d1, float& d2, float& d3,
                                                uint32_t a0, uint32_t a1, uint32_t a2, uint32_t a3,
                                                uint32_t b0, uint32_t b1) {
    asm volatile("mma.sync.aligned.m16n8k16.row.col.f32.f16.f16.f32 "
                 "{%0,%1,%2,%3}, {%4,%5,%6,%7}, {%8,%9}, {%0,%1,%2,%3};"
                 : "+f"(d0), "+f"(d1), "+f"(d2), "+f"(d3)
                 : "r"(a0), "r"(a1), "r"(a2), "r"(a3), "r"(b0), "r"(b1));
}

// out[m][n] = act( sum_k (X[m][k] (+ pre[k])) * W[n][k] (+ bias[n]) ), fp16 output.
// Tensor-core tf(fp16) hi/lo 3-pass for ~fp32 accuracy. CTA tile 128x128, K=128.
template<bool PRE, bool BIAS, bool TANH>
__global__ void __launch_bounds__(GEMM_T) gemm_mma(
    const float* __restrict__ X, const float* __restrict__ W,
    const float* __restrict__ bias, const float* __restrict__ pre,
    __half* __restrict__ out, int M)
{
    extern __shared__ __half sm[];
    __half* Xhi = sm;
    __half* Xlo = Xhi + 128 * LDH;
    __half* Whi = Xlo + 128 * LDH;
    __half* Wlo = Whi + 128 * LDH;

    const int tid  = threadIdx.x;
    const int row0 = blockIdx.x * 128;

    // Stage X tile: fp32 -> hi/lo fp16 split (PRE folded before split)
    #pragma unroll 4
    for (int idx = tid; idx < 128 * 128; idx += GEMM_T) {
        int m = idx >> 7, k = idx & 127;
        int gm = row0 + m;
        float v = (gm < M) ? X[(size_t)gm * D + k] : 0.f;
        if (PRE) v += __ldg(pre + k);
        __half hi = __float2half_rn(v);
        __half lo = __float2half_rn(v - __half2float(hi));
        Xhi[m * LDH + k] = hi;
        Xlo[m * LDH + k] = lo;
    }
    // Stage W (full 128x128): hi/lo split
    #pragma unroll 4
    for (int idx = tid; idx < 128 * 128; idx += GEMM_T) {
        int n = idx >> 7, k = idx & 127;
        float v = W[(size_t)n * D + k];
        __half hi = __float2half_rn(v);
        __half lo = __float2half_rn(v - __half2float(hi));
        Whi[n * LDH + k] = hi;
        Wlo[n * LDH + k] = lo;
    }
    __syncthreads();

    const int lane = tid & 31;
    const int wid  = tid >> 5;
    const int wm   = wid >> 1;   // 0..3 -> 32-row band
    const int wn   = wid & 1;    // 0..1 -> 64-col band

    // ldmatrix source addresses (k0 = 0 bases; advance by 32B per k-step)
    // A (x4): groups g = lane>>3: tiles (m0-7,k0),(m8-15,k0),(m0-7,k0+8),(m8-15,k0+8)
    const int ag    = lane >> 3;
    const int arow  = wm * 32 + (ag & 1) * 8 + (lane & 7);
    const int acol  = (ag >> 1) * 8;
    uint32_t aHiBase[2], aLoBase[2];
    #pragma unroll
    for (int mf = 0; mf < 2; mf++) {
        aHiBase[mf] = smem_u32(Xhi + (arow + mf * 16) * LDH + acol);
        aLoBase[mf] = smem_u32(Xlo + (arow + mf * 16) * LDH + acol);
    }
    // B (x2): threads 0-15: tiles (n0-7,k0),(n0-7,k0+8); rows are W's n rows
    const int bg   = (lane >> 3) & 1;
    const int brow = wn * 64 + (lane & 7);
    const int bcol = bg * 8;
    const uint32_t bHiBase = smem_u32(Whi + brow * LDH + bcol);
    const uint32_t bLoBase = smem_u32(Wlo + brow * LDH + bcol);

    float acc[2][8][4];
    #pragma unroll
    for (int mf = 0; mf < 2; mf++)
        #pragma unroll
        for (int nf = 0; nf < 8; nf++)
            #pragma unroll
            for (int c = 0; c < 4; c++) acc[mf][nf][c] = 0.f;

    #pragma unroll
    for (int ks = 0; ks < 8; ks++) {          // k0 = ks*16
        const uint32_t koff = ks * 16 * sizeof(__half);
        uint32_t ahi[2][4], alo[2][4];
        #pragma unroll
        for (int mf = 0; mf < 2; mf++) {
            ldsm_x4(ahi[mf][0], ahi[mf][1], ahi[mf][2], ahi[mf][3], aHiBase[mf] + koff);
            ldsm_x4(alo[mf][0], alo[mf][1], alo[mf][2], alo[mf][3], aLoBase[mf] + koff);
        }
        uint32_t bhi[8][2], blo[8][2];
        #pragma unroll
        for (int nf = 0; nf < 8; nf++) {
            const uint32_t noff = nf * 8 * LDH * sizeof(__half);
            ldsm_x2(bhi[nf][0], bhi[nf][1], bHiBase + noff + koff);
            ldsm_x2(blo[nf][0], blo[nf][1], bLoBase + noff + koff);
        }
        #pragma unroll
        for (int nf = 0; nf < 8; nf++)
            #pragma unroll
            for (int mf = 0; mf < 2; mf++) {
                mma16816(acc[mf][nf][0], acc[mf][nf][1], acc[mf][nf][2], acc[mf][nf][3],
                         ahi[mf][0], ahi[mf][1], ahi[mf][2], ahi[mf][3],
                         bhi[nf][0], bhi[nf][1]);
                mma16816(acc[mf][nf][0], acc[mf][nf][1], acc[mf][nf][2], acc[mf][nf][3],
                         ahi[mf][0], ahi[mf][1], ahi[mf][2], ahi[mf][3],
                         blo[nf][0], blo[nf][1]);
                mma16816(acc[mf][nf][0], acc[mf][nf][1], acc[mf][nf][2], acc[mf][nf][3],
                         alo[mf][0], alo[mf][1], alo[mf][2], alo[mf][3],
                         bhi[nf][0], bhi[nf][1]);
            }
    }

    // Epilogue: bias, tanh, fp16 store
    #pragma unroll
    for (int mf = 0; mf < 2; mf++) {
        const int r0 = row0 + wm * 32 + mf * 16 + (lane >> 2);
        const int r1 = r0 + 8;
        #pragma unroll
        for (int nf = 0; nf < 8; nf++) {
            const int col = wn * 64 + nf * 8 + 2 * (lane & 3);
            float v0 = acc[mf][nf][0], v1 = acc[mf][nf][1];
            float v2 = acc[mf][nf][2], v3 = acc[mf][nf][3];
            if (BIAS) {
                float b0 = __ldg(bias + col), b1 = __ldg(bias + col + 1);
                v0 += b0; v1 += b1; v2 += b0; v3 += b1;
            }
            if (TANH) { v0 = tanhf(v0); v1 = tanhf(v1); v2 = tanhf(v2); v3 = tanhf(v3); }
            if (r0 < M) *(__half2*)(out + (size_t)r0 * D + col) = __floats2half2_rn(v0, v1);
            if (r1 < M) *(__half2*)(out + (size_t)r1 * D + col) = __floats2half2_rn(v2, v3);
        }
    }
}

// One warp per user: w_l = (i_l>0) * (Q[u] . Ktab[i_l]);
// out[u] = sum_l w_l * tanh(A[i_l] + B[o_l])   (tables fp16, math fp32)
__global__ void __launch_bounds__(256) attend_kernel(
    const int* __restrict__ item_seqs,
    const int* __restrict__ opin_seqs,
    float* __restrict__ out, int U, int L)
{
    const int gw   = (int)((blockIdx.x * blockDim.x + threadIdx.x) >> 5);
    const int lane = threadIdx.x & 31;
    if (gw >= U) return;

    // lane covers cols [lane*4, lane*4+4)
    uint2 qw = *(const uint2*)(g_Q + (size_t)gw * D + lane * 4);
    float2 q01 = __half22float2(*reinterpret_cast<__half2*>(&qw.x));
    float2 q23 = __half22float2(*reinterpret_cast<__half2*>(&qw.y));

    float4 acc = make_float4(0.f, 0.f, 0.f, 0.f);
    const int* is = item_seqs + (size_t)gw * L;
    const int* os = opin_seqs + (size_t)gw * L;

    #pragma unroll 2
    for (int l = 0; l < L; ++l) {
        int i = __ldg(is + l);
        if (i > 0) {   // warp-uniform
            int o = __ldg(os + l);
            uint2 kw = *(const uint2*)(g_Ktab + (size_t)i * D + lane * 4);
            float2 k01 = __half22float2(*reinterpret_cast<__half2*>(&kw.x));
            float2 k23 = __half22float2(*reinterpret_cast<__half2*>(&kw.y));
            float w = q01.x * k01.x + q01.y * k01.y + q23.x * k23.x + q23.y * k23.y;
            #pragma unroll
            for (int s = 16; s; s >>= 1)
                w += __shfl_xor_sync(0xffffffffu, w, s);
            uint2 aw = *(const uint2*)(g_A + (size_t)i * D + lane * 4);
            uint2 bw = *(const uint2*)(g_B + (size_t)o * D + lane * 4);
            float2 a01 = __half22float2(*reinterpret_cast<__half2*>(&aw.x));
            float2 a23 = __half22float2(*reinterpret_cast<__half2*>(&aw.y));
            float2 b01 = __half22float2(*reinterpret_cast<__half2*>(&bw.x));
            float2 b23 = __half22float2(*reinterpret_cast<__half2*>(&bw.y));
            acc.x += w * tanhf(a01.x + b01.x);
            acc.y += w * tanhf(a01.y + b01.y);
            acc.z += w * tanhf(a23.x + b23.x);
            acc.w += w * tanhf(a23.y + b23.y);
        }
    }
    *(float4*)(out + (size_t)gw * D + lane * 4) = acc;
}

extern "C" void kernel_launch(void* const* d_in, const int* in_sizes, int n_in,
                              void* d_out, int out_size)
{
    const float* item_table = (const float*)d_in[0];
    const float* opin_table = (const float*)d_in[1];
    const float* user_emb   = (const float*)d_in[2];
    const float* attr       = (const float*)d_in[3];
    const float* Wq         = (const float*)d_in[4];
    const float* bq         = (const float*)d_in[5];
    const float* Wk         = (const float*)d_in[6];
    const float* bk         = (const float*)d_in[7];
    const float* Wv         = (const float*)d_in[8];
    const float* bv         = (const float*)d_in[9];
    const int*   item_seqs  = (const int*)d_in[10];
    const int*   opin_seqs  = (const int*)d_in[11];
    float*       out        = (float*)d_out;

    const int n_item = in_sizes[0] / D;
    const int n_opi  = in_sizes[1] / D;
    const int U      = in_sizes[2] / D;
    const int L      = in_sizes[10] / U;

    __half *pK, *pA, *pB, *pQ;
    cudaGetSymbolAddress((void**)&pK, g_Ktab);
    cudaGetSymbolAddress((void**)&pA, g_A);
    cudaGetSymbolAddress((void**)&pB, g_B);
    cudaGetSymbolAddress((void**)&pQ, g_Q);

    const int smemB = 4 * 128 * LDH * sizeof(__half);   // ~139 KB
    cudaFuncSetAttribute((const void*)gemm_mma<true,  true,  true >,
                         cudaFuncAttributeMaxDynamicSharedMemorySize, smemB);
    cudaFuncSetAttribute((const void*)gemm_mma<false, false, false>,
                         cudaFuncAttributeMaxDynamicSharedMemorySize, smemB);
    cudaFuncSetAttribute((const void*)gemm_mma<false, true,  false>,
                         cudaFuncAttributeMaxDynamicSharedMemorySize, smemB);
    cudaFuncSetAttribute((const void*)gemm_mma<false, true,  true >,
                         cudaFuncAttributeMaxDynamicSharedMemorySize, smemB);

    // Ktab[i] = tanh((attr + item[i]) @ Wk^T + bk)
    gemm_mma<true, true, true><<<(n_item + 127) / 128, GEMM_T, smemB>>>(
        item_table, Wk, bk, attr, pK, n_item);
    // A[i] = item[i] @ Wv^T
    gemm_mma<false, false, false><<<(n_item + 127) / 128, GEMM_T, smemB>>>(
        item_table, Wv, nullptr, nullptr, pA, n_item);
    // B[o] = opin[o] @ Wv^T + bv
    gemm_mma<false, true, false><<<(n_opi + 127) / 128, GEMM_T, smemB>>>(
        opin_table, Wv, bv, nullptr, pB, n_opi);
    // Q[u] = tanh(user[u] @ Wq^T + bq)
    gemm_mma<false, true, true><<<(U + 127) / 128, GEMM_T, smemB>>>(
        user_emb, Wq, bq, nullptr, pQ, U);

    // Attention/aggregation pass: one warp per user
    const int threads = 256;
    const int blocks  = (U * 32 + threads - 1) / threads;
    attend_kernel<<<blocks, threads>>>(item_seqs, opin_seqs, out, U, L);
}

// round 6
// speedup vs baseline: 1.8554x; 1.8554x over previous
#include <cuda_runtime.h>
#include <cuda_fp16.h>
#include <cstdint>

#define D    128
#define LDH  136              // half row stride in smem (8-half pad -> conflict-free ldmatrix)
#define TILE_B (128 * LDH * 2)  // 34816 bytes per staged 128x128 fp16 tile

// fp16 scratch tables (allocation-free __device__ globals)
__device__ __half g_Ktab[50000 * D];   // tanh((attr + item) @ Wk^T + bk)
__device__ __half g_A   [50000 * D];   // item @ Wv^T
__device__ __half g_B   [ 5000 * D];   // opin @ Wv^T + bv
__device__ __half g_Q   [10000 * D];   // tanh(user @ Wq^T + bq)

static __device__ __forceinline__ uint32_t smem_u32(const void* p) {
    return (uint32_t)__cvta_generic_to_shared(p);
}
static __device__ __forceinline__ void ldsm_x4(uint32_t& r0, uint32_t& r1,
                                               uint32_t& r2, uint32_t& r3, uint32_t addr) {
    asm volatile("ldmatrix.sync.aligned.m8n8.x4.shared.b16 {%0,%1,%2,%3}, [%4];"
                 : "=r"(r0), "=r"(r1), "=r"(r2), "=r"(r3) : "r"(addr));
}
static __device__ __forceinline__ void mma16816(float* d,
                                                const uint32_t* a, const uint32_t* b) {
    asm volatile("mma.sync.aligned.m16n8k16.row.col.f32.f16.f16.f32 "
                 "{%0,%1,%2,%3}, {%4,%5,%6,%7}, {%8,%9}, {%0,%1,%2,%3};"
                 : "+f"(d[0]), "+f"(d[1]), "+f"(d[2]), "+f"(d[3])
                 : "r"(a[0]), "r"(a[1]), "r"(a[2]), "r"(a[3]), "r"(b[0]), "r"(b[1]));
}

// Stage a 128x128 fp32 tile as hi/lo fp16 into padded smem (512 threads).
static __device__ __forceinline__ void stage_hilo(__half* hi, __half* lo,
    const float* __restrict__ src, int row0, int M, int tid)
{
    #pragma unroll
    for (int idx = tid; idx < 128 * 32; idx += 512) {
        int r  = idx >> 5;
        int c4 = (idx & 31) << 2;
        int gr = row0 + r;
        float4 v = make_float4(0.f, 0.f, 0.f, 0.f);
        if (gr < M) v = *(const float4*)(src + (size_t)gr * D + c4);
        __half h0 = __float2half_rn(v.x), h1 = __float2half_rn(v.y);
        __half h2 = __float2half_rn(v.z), h3 = __float2half_rn(v.w);
        __half l0 = __float2half_rn(v.x - __half2float(h0));
        __half l1 = __float2half_rn(v.y - __half2float(h1));
        __half l2 = __float2half_rn(v.z - __half2float(h2));
        __half l3 = __float2half_rn(v.w - __half2float(h3));
        __half2 ph0 = __halves2half2(h0, h1), ph1 = __halves2half2(h2, h3);
        __half2 pl0 = __halves2half2(l0, l1), pl1 = __halves2half2(l2, l3);
        uint2 uh, ul;
        uh.x = *(uint32_t*)&ph0; uh.y = *(uint32_t*)&ph1;
        ul.x = *(uint32_t*)&pl0; ul.y = *(uint32_t*)&pl1;
        *(uint2*)(hi + r * LDH + c4) = uh;
        *(uint2*)(lo + r * LDH + c4) = ul;
    }
}

// out_j[m][n] = act_j( sum_k X[m][k]*Wj[n][k] + ebias_j[n] ), fp16 outputs.
// ebias_0[n] = b0[n] + (HASPRE ? attr . W0[n,:] : 0); ebias_1 = 0.
// 512 threads; 16 warps in 4x4 grid of 32x32 warp tiles; hi/lo fp16 3-pass.
template<int NW, bool TANH0, bool TANH1, bool HASPRE>
__global__ void __launch_bounds__(512) tab_gemm(
    const float* __restrict__ X,
    const float* __restrict__ W0, const float* __restrict__ b0,
    const float* __restrict__ pre,
    const float* __restrict__ W1,
    __half* __restrict__ out0, __half* __restrict__ out1, int M)
{
    extern __shared__ char smc[];
    float*  eb  = (float*)smc;                 // NW*128 floats
    __half* Xhi = (__half*)(smc + 1024);
    __half* Xlo = (__half*)(smc + 1024 + TILE_B);
    __half* Wst = (__half*)(smc + 1024 + 2 * TILE_B);  // NW * (hi,lo) pairs

    const int tid  = threadIdx.x;
    const int lane = tid & 31;
    const int wid  = tid >> 5;
    const int wm   = wid >> 2;       // m band: 32 rows
    const int wn   = wid & 3;        // n band: 32 cols
    const int row0 = blockIdx.x * 128;

    // effective bias
    if (tid < 128) {
        float s = b0 ? __ldg(b0 + tid) : 0.f;
        if (HASPRE) {
            const float* wr = W0 + (size_t)tid * D;
            #pragma unroll 4
            for (int k = 0; k < D; k++) s += __ldg(pre + k) * __ldg(wr + k);
        }
        eb[tid] = s;
        if (NW == 2) eb[128 + tid] = 0.f;
    }

    stage_hilo(Xhi, Xlo, X, row0, M, tid);
    stage_hilo(Wst,              Wst +     128 * LDH, W0, 0, 128, tid);
    if (NW == 2)
        stage_hilo(Wst + 2 * 128 * LDH, Wst + 3 * 128 * LDH, W1, 0, 128, tid);
    __syncthreads();

    // ldmatrix lane-address mapping
    const int ag   = lane >> 3;
    const int arow = wm * 32 + (ag & 1) * 8 + (lane & 7);
    const int acol = (ag >> 1) * 8;
    const uint32_t aHi = smem_u32(Xhi + arow * LDH + acol);
    const uint32_t aLo = smem_u32(Xlo + arow * LDH + acol);
    const int brow = wn * 32 + (ag >> 1) * 8 + (lane & 7);
    const int bcol = (ag & 1) * 8;
    const uint32_t bOff = (uint32_t)(brow * LDH + bcol) * 2;  // bytes into a W tile

    #pragma unroll
    for (int j = 0; j < NW; j++) {
        const uint32_t bHi = smem_u32(Wst + j * 2 * 128 * LDH) + bOff;
        const uint32_t bLo = bHi + (uint32_t)TILE_B;

        float acc[2][4][4];
        #pragma unroll
        for (int mf = 0; mf < 2; mf++)
            #pragma unroll
            for (int nf = 0; nf < 4; nf++)
                #pragma unroll
                for (int c = 0; c < 4; c++) acc[mf][nf][c] = 0.f;

        #pragma unroll
        for (int ks = 0; ks < 8; ks++) {
            const uint32_t ko = (uint32_t)ks * 32;   // 16 halfs = 32 bytes
            uint32_t ahi[2][4], alo[2][4];
            #pragma unroll
            for (int mf = 0; mf < 2; mf++) {
                const uint32_t mo = (uint32_t)(mf * 16 * LDH) * 2;
                ldsm_x4(ahi[mf][0], ahi[mf][1], ahi[mf][2], ahi[mf][3], aHi + mo + ko);
                ldsm_x4(alo[mf][0], alo[mf][1], alo[mf][2], alo[mf][3], aLo + mo + ko);
            }
            uint32_t bhi[4][2], blo[4][2];
            #pragma unroll
            for (int nh = 0; nh < 2; nh++) {
                const uint32_t no = (uint32_t)(nh * 16 * LDH) * 2;
                ldsm_x4(bhi[nh*2][0], bhi[nh*2][1], bhi[nh*2+1][0], bhi[nh*2+1][1], bHi + no + ko);
                ldsm_x4(blo[nh*2][0], blo[nh*2][1], blo[nh*2+1][0], blo[nh*2+1][1], bLo + no + ko);
            }
            #pragma unroll
            for (int mf = 0; mf < 2; mf++)
                #pragma unroll
                for (int nf = 0; nf < 4; nf++) {
                    mma16816(acc[mf][nf], ahi[mf], bhi[nf]);   // hi * Whi
                    mma16816(acc[mf][nf], ahi[mf], blo[nf]);   // hi * Wlo
                    mma16816(acc[mf][nf], alo[mf], bhi[nf]);   // lo * Whi
                }
        }

        // epilogue
        __half* outp = (j == 0) ? out0 : out1;
        const bool T = (j == 0) ? TANH0 : TANH1;
        const float* ebj = eb + j * 128;
        #pragma unroll
        for (int mf = 0; mf < 2; mf++) {
            const int r0 = row0 + wm * 32 + mf * 16 + (lane >> 2);
            const int r1 = r0 + 8;
            #pragma unroll
            for (int nf = 0; nf < 4; nf++) {
                const int col = wn * 32 + nf * 8 + 2 * (lane & 3);
                float e0 = ebj[col], e1 = ebj[col + 1];
                float v0 = acc[mf][nf][0] + e0, v1 = acc[mf][nf][1] + e1;
                float v2 = acc[mf][nf][2] + e0, v3 = acc[mf][nf][3] + e1;
                if (T) { v0 = tanhf(v0); v1 = tanhf(v1); v2 = tanhf(v2); v3 = tanhf(v3); }
                if (r0 < M) *(__half2*)(outp + (size_t)r0 * D + col) = __floats2half2_rn(v0, v1);
                if (r1 < M) *(__half2*)(outp + (size_t)r1 * D + col) = __floats2half2_rn(v2, v3);
            }
        }
    }
}

// One warp per user: w_l = (i_l>0) * (Q[u].Ktab[i_l]); out[u] = sum_l w_l*tanh(A[i_l]+B[o_l])
__global__ void __launch_bounds__(256) attend_kernel(
    const int* __restrict__ item_seqs,
    const int* __restrict__ opin_seqs,
    float* __restrict__ out, int U, int L)
{
    const int gw   = (int)((blockIdx.x * blockDim.x + threadIdx.x) >> 5);
    const int lane = threadIdx.x & 31;
    if (gw >= U) return;

    uint2 qw = *(const uint2*)(g_Q + (size_t)gw * D + lane * 4);
    float2 q01 = __half22float2(*reinterpret_cast<__half2*>(&qw.x));
    float2 q23 = __half22float2(*reinterpret_cast<__half2*>(&qw.y));

    float4 acc = make_float4(0.f, 0.f, 0.f, 0.f);
    const int* is = item_seqs + (size_t)gw * L;
    const int* os = opin_seqs + (size_t)gw * L;

    #pragma unroll 2
    for (int l = 0; l < L; ++l) {
        int i = __ldg(is + l);
        if (i > 0) {   // warp-uniform
            int o = __ldg(os + l);
            uint2 kw = *(const uint2*)(g_Ktab + (size_t)i * D + lane * 4);
            float2 k01 = __half22float2(*reinterpret_cast<__half2*>(&kw.x));
            float2 k23 = __half22float2(*reinterpret_cast<__half2*>(&kw.y));
            float w = q01.x * k01.x + q01.y * k01.y + q23.x * k23.x + q23.y * k23.y;
            #pragma unroll
            for (int s = 16; s; s >>= 1)
                w += __shfl_xor_sync(0xffffffffu, w, s);
            uint2 aw = *(const uint2*)(g_A + (size_t)i * D + lane * 4);
            uint2 bw = *(const uint2*)(g_B + (size_t)o * D + lane * 4);
            float2 a01 = __half22float2(*reinterpret_cast<__half2*>(&aw.x));
            float2 a23 = __half22float2(*reinterpret_cast<__half2*>(&aw.y));
            float2 b01 = __half22float2(*reinterpret_cast<__half2*>(&bw.x));
            float2 b23 = __half22float2(*reinterpret_cast<__half2*>(&bw.y));
            acc.x += w * tanhf(a01.x + b01.x);
            acc.y += w * tanhf(a01.y + b01.y);
            acc.z += w * tanhf(a23.x + b23.x);
            acc.w += w * tanhf(a23.y + b23.y);
        }
    }
    *(float4*)(out + (size_t)gw * D + lane * 4) = acc;
}

extern "C" void kernel_launch(void* const* d_in, const int* in_sizes, int n_in,
                              void* d_out, int out_size)
{
    const float* item_table = (const float*)d_in[0];
    const float* opin_table = (const float*)d_in[1];
    const float* user_emb   = (const float*)d_in[2];
    const float* attr       = (const float*)d_in[3];
    const float* Wq         = (const float*)d_in[4];
    const float* bq         = (const float*)d_in[5];
    const float* Wk         = (const float*)d_in[6];
    const float* bk         = (const float*)d_in[7];
    const float* Wv         = (const float*)d_in[8];
    const float* bv         = (const float*)d_in[9];
    const int*   item_seqs  = (const int*)d_in[10];
    const int*   opin_seqs  = (const int*)d_in[11];
    float*       out        = (float*)d_out;

    const int n_item = in_sizes[0] / D;
    const int n_opi  = in_sizes[1] / D;
    const int U      = in_sizes[2] / D;
    const int L      = in_sizes[10] / U;

    __half *pK, *pA, *pB, *pQ;
    cudaGetSymbolAddress((void**)&pK, g_Ktab);
    cudaGetSymbolAddress((void**)&pA, g_A);
    cudaGetSymbolAddress((void**)&pB, g_B);
    cudaGetSymbolAddress((void**)&pQ, g_Q);

    const int smem2 = 1024 + 6 * TILE_B;   // 209920 B
    const int smem1 = 1024 + 4 * TILE_B;   // 140288 B
    cudaFuncSetAttribute((const void*)tab_gemm<2, true,  false, true >,
                         cudaFuncAttributeMaxDynamicSharedMemorySize, smem2);
    cudaFuncSetAttribute((const void*)tab_gemm<1, false, false, false>,
                         cudaFuncAttributeMaxDynamicSharedMemorySize, smem1);
    cudaFuncSetAttribute((const void*)tab_gemm<1, true,  false, false>,
                         cudaFuncAttributeMaxDynamicSharedMemorySize, smem1);

    // B = opin@Wv^T + bv   (small, launch first)
    tab_gemm<1, false, false, false><<<(n_opi + 127) / 128, 512, smem1>>>(
        opin_table, Wv, bv, nullptr, nullptr, pB, nullptr, n_opi);
    // Q = tanh(user@Wq^T + bq)
    tab_gemm<1, true, false, false><<<(U + 127) / 128, 512, smem1>>>(
        user_emb, Wq, bq, nullptr, nullptr, pQ, nullptr, U);
    // Fused item pass: Ktab = tanh(item@Wk^T + (bk + attr@Wk^T)), A = item@Wv^T
    tab_gemm<2, true, false, true><<<(n_item + 127) / 128, 512, smem2>>>(
        item_table, Wk, bk, attr, Wv, pK, pA, n_item);

    // Attention/aggregation pass: one warp per user
    const int threads = 256;
    const int blocks  = (U * 32 + threads - 1) / threads;
    attend_kernel<<<blocks, threads>>>(item_seqs, opin_seqs, out, U, L);
}

// round 7
// speedup vs baseline: 2.2645x; 1.2205x over previous
#include <cuda_runtime.h>
#include <cuda_fp16.h>
#include <cstdint>

#define D    128
#define LDH  136                // half row stride in smem (8-half pad, conflict-free ldmatrix)
#define TILE_B (128 * LDH * 2)  // 34816 bytes per staged 128x128 fp16 tile

// fp16 scratch tables (allocation-free __device__ globals)
__device__ __half g_Ktab[50000 * D];   // tanh((attr + item) @ Wk^T + bk)
__device__ __half g_A   [50000 * D];   // item @ Wv^T
__device__ __half g_B   [ 5000 * D];   // opin @ Wv^T + bv
__device__ __half g_Q   [10000 * D];   // tanh(user @ Wq^T + bq)

static __device__ __forceinline__ uint32_t smem_u32(const void* p) {
    return (uint32_t)__cvta_generic_to_shared(p);
}
static __device__ __forceinline__ void ldsm_x4(uint32_t& r0, uint32_t& r1,
                                               uint32_t& r2, uint32_t& r3, uint32_t addr) {
    asm volatile("ldmatrix.sync.aligned.m8n8.x4.shared.b16 {%0,%1,%2,%3}, [%4];"
                 : "=r"(r0), "=r"(r1), "=r"(r2), "=r"(r3) : "r"(addr));
}
static __device__ __forceinline__ void mma16816(float* d,
                                                const uint32_t* a, const uint32_t* b) {
    asm volatile("mma.sync.aligned.m16n8k16.row.col.f32.f16.f16.f32 "
                 "{%0,%1,%2,%3}, {%4,%5,%6,%7}, {%8,%9}, {%0,%1,%2,%3};"
                 : "+f"(d[0]), "+f"(d[1]), "+f"(d[2]), "+f"(d[3])
                 : "r"(a[0]), "r"(a[1]), "r"(a[2]), "r"(a[3]), "r"(b[0]), "r"(b[1]));
}

// fast accurate tanh: 1 - 2/(1+e^{2x}); exact at saturation, ~1e-6 rel error
static __device__ __forceinline__ float tanh_fast(float x) {
    float e = __expf(2.0f * x);
    return 1.0f - __fdividef(2.0f, 1.0f + e);
}

// Stage a 128x128 fp32 tile as hi/lo fp16 into padded smem (512 threads).
static __device__ __forceinline__ void stage_hilo(__half* hi, __half* lo,
    const float* __restrict__ src, int row0, int M, int tid)
{
    #pragma unroll
    for (int idx = tid; idx < 128 * 32; idx += 512) {
        int r  = idx >> 5;
        int c4 = (idx & 31) << 2;
        int gr = row0 + r;
        float4 v = make_float4(0.f, 0.f, 0.f, 0.f);
        if (gr < M) v = *(const float4*)(src + (size_t)gr * D + c4);
        __half h0 = __float2half_rn(v.x), h1 = __float2half_rn(v.y);
        __half h2 = __float2half_rn(v.z), h3 = __float2half_rn(v.w);
        __half l0 = __float2half_rn(v.x - __half2float(h0));
        __half l1 = __float2half_rn(v.y - __half2float(h1));
        __half l2 = __float2half_rn(v.z - __half2float(h2));
        __half l3 = __float2half_rn(v.w - __half2float(h3));
        __half2 ph0 = __halves2half2(h0, h1), ph1 = __halves2half2(h2, h3);
        __half2 pl0 = __halves2half2(l0, l1), pl1 = __halves2half2(l2, l3);
        uint2 uh, ul;
        uh.x = *(uint32_t*)&ph0; uh.y = *(uint32_t*)&ph1;
        ul.x = *(uint32_t*)&pl0; ul.y = *(uint32_t*)&pl1;
        *(uint2*)(hi + r * LDH + c4) = uh;
        *(uint2*)(lo + r * LDH + c4) = ul;
    }
}

// All three table GEMMs in ONE launch; role chosen by blockIdx.
// role item: out0=Ktab (tanh, ebias=bk+attr.Wk), out1=A (no bias/tanh), W0=Wk, W1=Wv
// role opin: out0=B (bias bv, no tanh), W0=Wv
// role user: out0=Q (bias bq, tanh), W0=Wq
__global__ void __launch_bounds__(512) tab_gemm_all(
    const float* __restrict__ item_table, const float* __restrict__ opin_table,
    const float* __restrict__ user_emb,   const float* __restrict__ attr,
    const float* __restrict__ Wq, const float* __restrict__ bq,
    const float* __restrict__ Wk, const float* __restrict__ bk,
    const float* __restrict__ Wv, const float* __restrict__ bv,
    __half* __restrict__ pK, __half* __restrict__ pA,
    __half* __restrict__ pB, __half* __restrict__ pQ,
    int n_item, int n_opi, int n_user, int nb_item, int nb_opi)
{
    extern __shared__ char smc[];
    float*  eb  = (float*)smc;                          // 2*128 floats
    __half* Xhi = (__half*)(smc + 1024);
    __half* Xlo = (__half*)(smc + 1024 + TILE_B);
    __half* Wst = (__half*)(smc + 1024 + 2 * TILE_B);   // up to 2 (hi,lo) W tiles

    const int tid  = threadIdx.x;
    const int lane = tid & 31;
    const int wid  = tid >> 5;
    const int wm   = wid >> 2;
    const int wn   = wid & 3;

    // role selection
    const int bid = blockIdx.x;
    const float *X, *W0, *b0, *pre = nullptr, *W1 = nullptr;
    __half *out0, *out1 = nullptr;
    int M, row0;
    bool two = false, tanh0, haspre = false;
    if (bid < nb_item) {
        X = item_table; W0 = Wk; b0 = bk; pre = attr; W1 = Wv;
        out0 = pK; out1 = pA; M = n_item; row0 = bid * 128;
        two = true; tanh0 = true; haspre = true;
    } else if (bid < nb_item + nb_opi) {
        X = opin_table; W0 = Wv; b0 = bv;
        out0 = pB; M = n_opi; row0 = (bid - nb_item) * 128; tanh0 = false;
    } else {
        X = user_emb; W0 = Wq; b0 = bq;
        out0 = pQ; M = n_user; row0 = (bid - nb_item - nb_opi) * 128; tanh0 = true;
    }

    // effective bias: eb0 = b0 (+ attr . W0[n,:]), eb1 = 0
    if (tid < 128) {
        float s = __ldg(b0 + tid);
        if (haspre) {
            const float* wr = W0 + (size_t)tid * D;
            #pragma unroll 4
            for (int k = 0; k < D; k++) s += __ldg(pre + k) * __ldg(wr + k);
        }
        eb[tid] = s;
        eb[128 + tid] = 0.f;
    }

    stage_hilo(Xhi, Xlo, X, row0, M, tid);
    stage_hilo(Wst, Wst + 128 * LDH, W0, 0, 128, tid);
    if (two) stage_hilo(Wst + 2 * 128 * LDH, Wst + 3 * 128 * LDH, W1, 0, 128, tid);
    __syncthreads();

    // ldmatrix lane-address mapping
    const int ag   = lane >> 3;
    const int arow = wm * 32 + (ag & 1) * 8 + (lane & 7);
    const int acol = (ag >> 1) * 8;
    const uint32_t aHi = smem_u32(Xhi + arow * LDH + acol);
    const uint32_t aLo = smem_u32(Xlo + arow * LDH + acol);
    const int brow = wn * 32 + (ag >> 1) * 8 + (lane & 7);
    const int bcol = (ag & 1) * 8;
    const uint32_t bOff  = (uint32_t)(brow * LDH + bcol) * 2;
    const uint32_t bHi0  = smem_u32(Wst) + bOff;
    const uint32_t bHi1  = smem_u32(Wst + 2 * 128 * LDH) + bOff;

    float acc[2][2][4][4];   // [j][mf][nf][c]
    #pragma unroll
    for (int j = 0; j < 2; j++)
        #pragma unroll
        for (int mf = 0; mf < 2; mf++)
            #pragma unroll
            for (int nf = 0; nf < 4; nf++)
                #pragma unroll
                for (int c = 0; c < 4; c++) acc[j][mf][nf][c] = 0.f;

    #pragma unroll
    for (int ks = 0; ks < 8; ks++) {
        const uint32_t ko = (uint32_t)ks * 32;   // 16 halfs = 32 bytes
        uint32_t ahi[2][4], alo[2][4];
        #pragma unroll
        for (int mf = 0; mf < 2; mf++) {
            const uint32_t mo = (uint32_t)(mf * 16 * LDH) * 2;
            ldsm_x4(ahi[mf][0], ahi[mf][1], ahi[mf][2], ahi[mf][3], aHi + mo + ko);
            ldsm_x4(alo[mf][0], alo[mf][1], alo[mf][2], alo[mf][3], aLo + mo + ko);
        }
        {   // j = 0
            uint32_t bhi[4][2], blo[4][2];
            #pragma unroll
            for (int nh = 0; nh < 2; nh++) {
                const uint32_t no = (uint32_t)(nh * 16 * LDH) * 2;
                ldsm_x4(bhi[nh*2][0], bhi[nh*2][1], bhi[nh*2+1][0], bhi[nh*2+1][1],
                        bHi0 + no + ko);
                ldsm_x4(blo[nh*2][0], blo[nh*2][1], blo[nh*2+1][0], blo[nh*2+1][1],
                        bHi0 + (uint32_t)TILE_B + no + ko);
            }
            #pragma unroll
            for (int mf = 0; mf < 2; mf++)
                #pragma unroll
                for (int nf = 0; nf < 4; nf++) {
                    mma16816(acc[0][mf][nf], ahi[mf], bhi[nf]);
                    mma16816(acc[0][mf][nf], ahi[mf], blo[nf]);
                    mma16816(acc[0][mf][nf], alo[mf], bhi[nf]);
                }
        }
        if (two) {   // j = 1
            uint32_t bhi[4][2], blo[4][2];
            #pragma unroll
            for (int nh = 0; nh < 2; nh++) {
                const uint32_t no = (uint32_t)(nh * 16 * LDH) * 2;
                ldsm_x4(bhi[nh*2][0], bhi[nh*2][1], bhi[nh*2+1][0], bhi[nh*2+1][1],
                        bHi1 + no + ko);
                ldsm_x4(blo[nh*2][0], blo[nh*2][1], blo[nh*2+1][0], blo[nh*2+1][1],
                        bHi1 + (uint32_t)TILE_B + no + ko);
            }
            #pragma unroll
            for (int mf = 0; mf < 2; mf++)
                #pragma unroll
                for (int nf = 0; nf < 4; nf++) {
                    mma16816(acc[1][mf][nf], ahi[mf], bhi[nf]);
                    mma16816(acc[1][mf][nf], ahi[mf], blo[nf]);
                    mma16816(acc[1][mf][nf], alo[mf], bhi[nf]);
                }
        }
    }

    // epilogue
    const int NW = two ? 2 : 1;
    for (int j = 0; j < NW; j++) {
        __half* outp = (j == 0) ? out0 : out1;
        const bool T = (j == 0) ? tanh0 : false;
        const float* ebj = eb + j * 128;
        #pragma unroll
        for (int mf = 0; mf < 2; mf++) {
            const int r0 = row0 + wm * 32 + mf * 16 + (lane >> 2);
            const int r1 = r0 + 8;
            #pragma unroll
            for (int nf = 0; nf < 4; nf++) {
                const int col = wn * 32 + nf * 8 + 2 * (lane & 3);
                float e0 = ebj[col], e1 = ebj[col + 1];
                float v0 = acc[j][mf][nf][0] + e0, v1 = acc[j][mf][nf][1] + e1;
                float v2 = acc[j][mf][nf][2] + e0, v3 = acc[j][mf][nf][3] + e1;
                if (T) { v0 = tanhf(v0); v1 = tanhf(v1); v2 = tanhf(v2); v3 = tanhf(v3); }
                if (r0 < M) *(__half2*)(outp + (size_t)r0 * D + col) = __floats2half2_rn(v0, v1);
                if (r1 < M) *(__half2*)(outp + (size_t)r1 * D + col) = __floats2half2_rn(v2, v3);
            }
        }
    }
}

// One warp per user, 2-step pipelined, branchless mask.
__global__ void __launch_bounds__(256) attend_kernel(
    const int* __restrict__ item_seqs,
    const int* __restrict__ opin_seqs,
    float* __restrict__ out, int U, int L)
{
    const int gw   = (int)((blockIdx.x * blockDim.x + threadIdx.x) >> 5);
    const int lane = threadIdx.x & 31;
    if (gw >= U) return;

    const uint2* Kt = (const uint2*)g_Ktab;   // 32 uint2 per row
    const uint2* At = (const uint2*)g_A;
    const uint2* Bt = (const uint2*)g_B;

    uint2 qw = *((const uint2*)g_Q + (size_t)gw * 32 + lane);
    float2 q01 = __half22float2(*reinterpret_cast<__half2*>(&qw.x));
    float2 q23 = __half22float2(*reinterpret_cast<__half2*>(&qw.y));

    float4 acc = make_float4(0.f, 0.f, 0.f, 0.f);
    const int* is = item_seqs + (size_t)gw * L;
    const int* os = opin_seqs + (size_t)gw * L;

    for (int l = 0; l < L; l += 2) {
        int i0 = __ldg(is + l),     i1 = __ldg(is + l + 1);
        int o0 = __ldg(os + l),     o1 = __ldg(os + l + 1);
        uint2 kw0 = __ldg(Kt + (size_t)i0 * 32 + lane);
        uint2 kw1 = __ldg(Kt + (size_t)i1 * 32 + lane);
        uint2 aw0 = __ldg(At + (size_t)i0 * 32 + lane);
        uint2 aw1 = __ldg(At + (size_t)i1 * 32 + lane);
        uint2 bw0 = __ldg(Bt + (size_t)o0 * 32 + lane);
        uint2 bw1 = __ldg(Bt + (size_t)o1 * 32 + lane);

        float2 k01 = __half22float2(*reinterpret_cast<__half2*>(&kw0.x));
        float2 k23 = __half22float2(*reinterpret_cast<__half2*>(&kw0.y));
        float w0 = q01.x * k01.x + q01.y * k01.y + q23.x * k23.x + q23.y * k23.y;
        k01 = __half22float2(*reinterpret_cast<__half2*>(&kw1.x));
        k23 = __half22float2(*reinterpret_cast<__half2*>(&kw1.y));
        float w1 = q01.x * k01.x + q01.y * k01.y + q23.x * k23.x + q23.y * k23.y;

        #pragma unroll
        for (int s = 16; s; s >>= 1) {
            w0 += __shfl_xor_sync(0xffffffffu, w0, s);
            w1 += __shfl_xor_sync(0xffffffffu, w1, s);
        }
        w0 = (i0 > 0) ? w0 : 0.f;
        w1 = (i1 > 0) ? w1 : 0.f;

        float2 a01 = __half22float2(*reinterpret_cast<__half2*>(&aw0.x));
        float2 a23 = __half22float2(*reinterpret_cast<__half2*>(&aw0.y));
        float2 b01 = __half22float2(*reinterpret_cast<__half2*>(&bw0.x));
        float2 b23 = __half22float2(*reinterpret_cast<__half2*>(&bw0.y));
        acc.x += w0 * tanh_fast(a01.x + b01.x);
        acc.y += w0 * tanh_fast(a01.y + b01.y);
        acc.z += w0 * tanh_fast(a23.x + b23.x);
        acc.w += w0 * tanh_fast(a23.y + b23.y);

        a01 = __half22float2(*reinterpret_cast<__half2*>(&aw1.x));
        a23 = __half22float2(*reinterpret_cast<__half2*>(&aw1.y));
        b01 = __half22float2(*reinterpret_cast<__half2*>(&bw1.x));
        b23 = __half22float2(*reinterpret_cast<__half2*>(&bw1.y));
        acc.x += w1 * tanh_fast(a01.x + b01.x);
        acc.y += w1 * tanh_fast(a01.y + b01.y);
        acc.z += w1 * tanh_fast(a23.x + b23.x);
        acc.w += w1 * tanh_fast(a23.y + b23.y);
    }
    *(float4*)(out + (size_t)gw * D + lane * 4) = acc;
}

extern "C" void kernel_launch(void* const* d_in, const int* in_sizes, int n_in,
                              void* d_out, int out_size)
{
    const float* item_table = (const float*)d_in[0];
    const float* opin_table = (const float*)d_in[1];
    const float* user_emb   = (const float*)d_in[2];
    const float* attr       = (const float*)d_in[3];
    const float* Wq         = (const float*)d_in[4];
    const float* bq         = (const float*)d_in[5];
    const float* Wk         = (const float*)d_in[6];
    const float* bk         = (const float*)d_in[7];
    const float* Wv         = (const float*)d_in[8];
    const float* bv         = (const float*)d_in[9];
    const int*   item_seqs  = (const int*)d_in[10];
    const int*   opin_seqs  = (const int*)d_in[11];
    float*       out        = (float*)d_out;

    const int n_item = in_sizes[0] / D;
    const int n_opi  = in_sizes[1] / D;
    const int U      = in_sizes[2] / D;
    const int L      = in_sizes[10] / U;

    __half *pK, *pA, *pB, *pQ;
    cudaGetSymbolAddress((void**)&pK, g_Ktab);
    cudaGetSymbolAddress((void**)&pA, g_A);
    cudaGetSymbolAddress((void**)&pB, g_B);
    cudaGetSymbolAddress((void**)&pQ, g_Q);

    const int nb_item = (n_item + 127) / 128;
    const int nb_opi  = (n_opi + 127) / 128;
    const int nb_user = (U + 127) / 128;

    const int smemB = 1024 + 6 * TILE_B;   // 209920 B
    cudaFuncSetAttribute((const void*)tab_gemm_all,
                         cudaFuncAttributeMaxDynamicSharedMemorySize, smemB);

    tab_gemm_all<<<nb_item + nb_opi + nb_user, 512, smemB>>>(
        item_table, opin_table, user_emb, attr,
        Wq, bq, Wk, bk, Wv, bv,
        pK, pA, pB, pQ, n_item, n_opi, U, nb_item, nb_opi);

    const int threads = 256;
    const int blocks  = (U * 32 + threads - 1) / threads;
    attend_kernel<<<blocks, threads>>>(item_seqs, opin_seqs, out, U, L);
}

// round 8
// speedup vs baseline: 2.5649x; 1.1327x over previous
#include <cuda_runtime.h>
#include <cuda_fp16.h>
#include <cstdint>

#define D    128
#define LDH  136                // half row stride in smem (8-half pad, conflict-free ldmatrix)
#define TILE_B (128 * LDH * 2)  // 34816 bytes per staged 128x128 fp16 tile

// fp16 scratch tables (allocation-free __device__ globals)
__device__ __half g_Ktab[50000 * D];   // tanh((attr + item) @ Wk^T + bk)
__device__ __half g_A   [50000 * D];   // item @ Wv^T
__device__ __half g_B   [ 5000 * D];   // opin @ Wv^T + bv
__device__ __half g_Q   [10000 * D];   // tanh(user @ Wq^T + bq)

// Preconverted weights (hi/lo fp16) + effective biases
__device__ __half g_Wh[3][128 * 128];  // 0: Wk, 1: Wv, 2: Wq
__device__ __half g_Wl[3][128 * 128];
__device__ float  g_eb[3][128];        // 0: bk + attr.Wk[n,:], 1: bv, 2: bq

static __device__ __forceinline__ uint32_t smem_u32(const void* p) {
    return (uint32_t)__cvta_generic_to_shared(p);
}
static __device__ __forceinline__ void ldsm_x4(uint32_t& r0, uint32_t& r1,
                                               uint32_t& r2, uint32_t& r3, uint32_t addr) {
    asm volatile("ldmatrix.sync.aligned.m8n8.x4.shared.b16 {%0,%1,%2,%3}, [%4];"
                 : "=r"(r0), "=r"(r1), "=r"(r2), "=r"(r3) : "r"(addr));
}
static __device__ __forceinline__ void mma16816(float* d,
                                                const uint32_t* a, const uint32_t* b) {
    asm volatile("mma.sync.aligned.m16n8k16.row.col.f32.f16.f16.f32 "
                 "{%0,%1,%2,%3}, {%4,%5,%6,%7}, {%8,%9}, {%0,%1,%2,%3};"
                 : "+f"(d[0]), "+f"(d[1]), "+f"(d[2]), "+f"(d[3])
                 : "r"(a[0]), "r"(a[1]), "r"(a[2]), "r"(a[3]), "r"(b[0]), "r"(b[1]));
}
static __device__ __forceinline__ float tanha(float x) {
    float y;
    asm("tanh.approx.f32 %0, %1;" : "=f"(y) : "f"(x));
    return y;
}

// ---------------- setup: preconvert W -> fp16 hi/lo, compute effective biases
__global__ void __launch_bounds__(256) setup_kernel(
    const float* __restrict__ Wk, const float* __restrict__ bk,
    const float* __restrict__ Wv, const float* __restrict__ bv,
    const float* __restrict__ Wq, const float* __restrict__ bq,
    const float* __restrict__ attr)
{
    const int j = blockIdx.x;
    const float* W = (j == 0) ? Wk : (j == 1) ? Wv : Wq;
    const float* b = (j == 0) ? bk : (j == 1) ? bv : bq;
    const int tid = threadIdx.x;

    #pragma unroll 4
    for (int idx = tid; idx < 128 * 32; idx += 256) {
        int e4 = idx << 2;
        float4 v = *(const float4*)(W + e4);
        __half h0 = __float2half_rn(v.x), h1 = __float2half_rn(v.y);
        __half h2 = __float2half_rn(v.z), h3 = __float2half_rn(v.w);
        __half l0 = __float2half_rn(v.x - __half2float(h0));
        __half l1 = __float2half_rn(v.y - __half2float(h1));
        __half l2 = __float2half_rn(v.z - __half2float(h2));
        __half l3 = __float2half_rn(v.w - __half2float(h3));
        __half2 ph0 = __halves2half2(h0, h1), ph1 = __halves2half2(h2, h3);
        __half2 pl0 = __halves2half2(l0, l1), pl1 = __halves2half2(l2, l3);
        uint2 uh, ul;
        uh.x = *(uint32_t*)&ph0; uh.y = *(uint32_t*)&ph1;
        ul.x = *(uint32_t*)&pl0; ul.y = *(uint32_t*)&pl1;
        *(uint2*)(&g_Wh[j][e4]) = uh;
        *(uint2*)(&g_Wl[j][e4]) = ul;
    }
    if (tid < 128) {
        float s = __ldg(b + tid);
        if (j == 0) {
            const float* wr = Wk + (size_t)tid * D;
            #pragma unroll 8
            for (int k = 0; k < D; k++) s += __ldg(attr + k) * __ldg(wr + k);
        }
        g_eb[j][tid] = s;
    }
}

// Stage a 128x128 fp32 tile as hi/lo fp16 into padded smem (512 threads).
static __device__ __forceinline__ void stage_hilo(__half* hi, __half* lo,
    const float* __restrict__ src, int row0, int M, int tid)
{
    #pragma unroll
    for (int idx = tid; idx < 128 * 32; idx += 512) {
        int r  = idx >> 5;
        int c4 = (idx & 31) << 2;
        int gr = row0 + r;
        float4 v = make_float4(0.f, 0.f, 0.f, 0.f);
        if (gr < M) v = *(const float4*)(src + (size_t)gr * D + c4);
        __half h0 = __float2half_rn(v.x), h1 = __float2half_rn(v.y);
        __half h2 = __float2half_rn(v.z), h3 = __float2half_rn(v.w);
        __half l0 = __float2half_rn(v.x - __half2float(h0));
        __half l1 = __float2half_rn(v.y - __half2float(h1));
        __half l2 = __float2half_rn(v.z - __half2float(h2));
        __half l3 = __float2half_rn(v.w - __half2float(h3));
        __half2 ph0 = __halves2half2(h0, h1), ph1 = __halves2half2(h2, h3);
        __half2 pl0 = __halves2half2(l0, l1), pl1 = __halves2half2(l2, l3);
        uint2 uh, ul;
        uh.x = *(uint32_t*)&ph0; uh.y = *(uint32_t*)&ph1;
        ul.x = *(uint32_t*)&pl0; ul.y = *(uint32_t*)&pl1;
        *(uint2*)(hi + r * LDH + c4) = uh;
        *(uint2*)(lo + r * LDH + c4) = ul;
    }
}

// Copy a preconverted 128x128 fp16 tile into padded smem.
static __device__ __forceinline__ void stage_w(__half* dst, const __half* __restrict__ src,
                                               int tid)
{
    #pragma unroll
    for (int idx = tid; idx < 128 * 16; idx += 512) {
        int r = idx >> 4;
        int c = (idx & 15) << 3;
        *(uint4*)(dst + r * LDH + c) = *(const uint4*)(src + r * 128 + c);
    }
}

// All three table GEMMs in ONE launch; 256 rows per CTA (two 128-row sub-tiles).
__global__ void __launch_bounds__(512) tab_gemm_all(
    const float* __restrict__ item_table, const float* __restrict__ opin_table,
    const float* __restrict__ user_emb,
    __half* __restrict__ pK, __half* __restrict__ pA,
    __half* __restrict__ pB, __half* __restrict__ pQ,
    int n_item, int n_opi, int n_user, int nb_item, int nb_opi)
{
    extern __shared__ char smc[];
    __half* Xhi = (__half*)smc;
    __half* Xlo = (__half*)(smc + TILE_B);
    __half* Wsm = (__half*)(smc + 2 * TILE_B);   // up to 2 (hi,lo) W tile pairs

    const int tid  = threadIdx.x;
    const int lane = tid & 31;
    const int wid  = tid >> 5;
    const int wm   = wid >> 2;
    const int wn   = wid & 3;

    // role selection
    const int bid = blockIdx.x;
    const float* X;
    __half *out0, *out1 = nullptr;
    int M, rbase, jw0, jw1 = -1;
    bool two = false, tanh0;
    if (bid < nb_item) {
        X = item_table; out0 = pK; out1 = pA; M = n_item;
        rbase = bid * 256; jw0 = 0; jw1 = 1; two = true; tanh0 = true;
    } else if (bid < nb_item + nb_opi) {
        X = opin_table; out0 = pB; M = n_opi;
        rbase = (bid - nb_item) * 256; jw0 = 1; tanh0 = false;
    } else {
        X = user_emb; out0 = pQ; M = n_user;
        rbase = (bid - nb_item - nb_opi) * 256; jw0 = 2; tanh0 = true;
    }

    // stage W tiles (from preconverted fp16 globals)
    stage_w(Wsm,               g_Wh[jw0], tid);
    stage_w(Wsm + 128 * LDH,   g_Wl[jw0], tid);
    if (two) {
        stage_w(Wsm + 2 * 128 * LDH, g_Wh[jw1], tid);
        stage_w(Wsm + 3 * 128 * LDH, g_Wl[jw1], tid);
    }

    // ldmatrix lane-address mapping
    const int ag   = lane >> 3;
    const int arow = wm * 32 + (ag & 1) * 8 + (lane & 7);
    const int acol = (ag >> 1) * 8;
    const uint32_t aHi = smem_u32(Xhi + arow * LDH + acol);
    const uint32_t aLo = smem_u32(Xlo + arow * LDH + acol);
    const int brow = wn * 32 + (ag >> 1) * 8 + (lane & 7);
    const int bcol = (ag & 1) * 8;
    const uint32_t bOff = (uint32_t)(brow * LDH + bcol) * 2;
    const uint32_t bHi0 = smem_u32(Wsm) + bOff;
    const uint32_t bHi1 = smem_u32(Wsm + 2 * 128 * LDH) + bOff;

    #pragma unroll 1
    for (int sub = 0; sub < 2; sub++) {
        const int row0 = rbase + sub * 128;
        if (row0 >= M) break;

        stage_hilo(Xhi, Xlo, X, row0, M, tid);
        __syncthreads();

        float acc[2][2][4][4];   // [j][mf][nf][c]
        #pragma unroll
        for (int j = 0; j < 2; j++)
            #pragma unroll
            for (int mf = 0; mf < 2; mf++)
                #pragma unroll
                for (int nf = 0; nf < 4; nf++)
                    #pragma unroll
                    for (int c = 0; c < 4; c++) acc[j][mf][nf][c] = 0.f;

        #pragma unroll
        for (int ks = 0; ks < 8; ks++) {
            const uint32_t ko = (uint32_t)ks * 32;
            uint32_t ahi[2][4], alo[2][4];
            #pragma unroll
            for (int mf = 0; mf < 2; mf++) {
                const uint32_t mo = (uint32_t)(mf * 16 * LDH) * 2;
                ldsm_x4(ahi[mf][0], ahi[mf][1], ahi[mf][2], ahi[mf][3], aHi + mo + ko);
                ldsm_x4(alo[mf][0], alo[mf][1], alo[mf][2], alo[mf][3], aLo + mo + ko);
            }
            {   // j = 0
                uint32_t bhi[4][2], blo[4][2];
                #pragma unroll
                for (int nh = 0; nh < 2; nh++) {
                    const uint32_t no = (uint32_t)(nh * 16 * LDH) * 2;
                    ldsm_x4(bhi[nh*2][0], bhi[nh*2][1], bhi[nh*2+1][0], bhi[nh*2+1][1],
                            bHi0 + no + ko);
                    ldsm_x4(blo[nh*2][0], blo[nh*2][1], blo[nh*2+1][0], blo[nh*2+1][1],
                            bHi0 + (uint32_t)TILE_B + no + ko);
                }
                #pragma unroll
                for (int mf = 0; mf < 2; mf++)
                    #pragma unroll
                    for (int nf = 0; nf < 4; nf++) {
                        mma16816(acc[0][mf][nf], ahi[mf], bhi[nf]);
                        mma16816(acc[0][mf][nf], ahi[mf], blo[nf]);
                        mma16816(acc[0][mf][nf], alo[mf], bhi[nf]);
                    }
            }
            if (two) {   // j = 1
                uint32_t bhi[4][2], blo[4][2];
                #pragma unroll
                for (int nh = 0; nh < 2; nh++) {
                    const uint32_t no = (uint32_t)(nh * 16 * LDH) * 2;
                    ldsm_x4(bhi[nh*2][0], bhi[nh*2][1], bhi[nh*2+1][0], bhi[nh*2+1][1],
                            bHi1 + no + ko);
                    ldsm_x4(blo[nh*2][0], blo[nh*2][1], blo[nh*2+1][0], blo[nh*2+1][1],
                            bHi1 + (uint32_t)TILE_B + no + ko);
                }
                #pragma unroll
                for (int mf = 0; mf < 2; mf++)
                    #pragma unroll
                    for (int nf = 0; nf < 4; nf++) {
                        mma16816(acc[1][mf][nf], ahi[mf], bhi[nf]);
                        mma16816(acc[1][mf][nf], ahi[mf], blo[nf]);
                        mma16816(acc[1][mf][nf], alo[mf], bhi[nf]);
                    }
            }
        }
        __syncthreads();   // all ldsm done; Xhi/Xlo free for next sub-tile

        // epilogue
        const int NW = two ? 2 : 1;
        for (int j = 0; j < NW; j++) {
            __half* outp = (j == 0) ? out0 : out1;
            const bool T = (j == 0) ? tanh0 : false;
            const bool hasb = (j == 0);
            const float* ebj = g_eb[(j == 0) ? jw0 : jw1];
            #pragma unroll
            for (int mf = 0; mf < 2; mf++) {
                const int r0 = row0 + wm * 32 + mf * 16 + (lane >> 2);
                const int r1 = r0 + 8;
                #pragma unroll
                for (int nf = 0; nf < 4; nf++) {
                    const int col = wn * 32 + nf * 8 + 2 * (lane & 3);
                    float e0 = hasb ? __ldg(ebj + col)     : 0.f;
                    float e1 = hasb ? __ldg(ebj + col + 1) : 0.f;
                    float v0 = acc[j][mf][nf][0] + e0, v1 = acc[j][mf][nf][1] + e1;
                    float v2 = acc[j][mf][nf][2] + e0, v3 = acc[j][mf][nf][3] + e1;
                    if (T) { v0 = tanhf(v0); v1 = tanhf(v1); v2 = tanhf(v2); v3 = tanhf(v3); }
                    if (r0 < M) *(__half2*)(outp + (size_t)r0 * D + col) = __floats2half2_rn(v0, v1);
                    if (r1 < M) *(__half2*)(outp + (size_t)r1 * D + col) = __floats2half2_rn(v2, v3);
                }
            }
        }
    }
}

// One warp per user, 2-step pipelined, branchless mask, half2 adds + HW tanh.
__global__ void __launch_bounds__(256) attend_kernel(
    const int* __restrict__ item_seqs,
    const int* __restrict__ opin_seqs,
    float* __restrict__ out, int U, int L)
{
    const int gw   = (int)((blockIdx.x * blockDim.x + threadIdx.x) >> 5);
    const int lane = threadIdx.x & 31;
    if (gw >= U) return;

    const uint2* Kt = (const uint2*)g_Ktab;   // 32 uint2 per row
    const uint2* At = (const uint2*)g_A;
    const uint2* Bt = (const uint2*)g_B;

    uint2 qw = *((const uint2*)g_Q + (size_t)gw * 32 + lane);
    float2 q01 = __half22float2(*reinterpret_cast<__half2*>(&qw.x));
    float2 q23 = __half22float2(*reinterpret_cast<__half2*>(&qw.y));

    float4 acc = make_float4(0.f, 0.f, 0.f, 0.f);
    const int* is = item_seqs + (size_t)gw * L;
    const int* os = opin_seqs + (size_t)gw * L;

    for (int l = 0; l < L; l += 2) {
        int i0 = __ldg(is + l),     i1 = __ldg(is + l + 1);
        int o0 = __ldg(os + l),     o1 = __ldg(os + l + 1);
        uint2 kw0 = __ldg(Kt + (size_t)i0 * 32 + lane);
        uint2 kw1 = __ldg(Kt + (size_t)i1 * 32 + lane);
        uint2 aw0 = __ldg(At + (size_t)i0 * 32 + lane);
        uint2 aw1 = __ldg(At + (size_t)i1 * 32 + lane);
        uint2 bw0 = __ldg(Bt + (size_t)o0 * 32 + lane);
        uint2 bw1 = __ldg(Bt + (size_t)o1 * 32 + lane);

        // q . k in fp32 (protect the weight path)
        float2 k01 = __half22float2(*reinterpret_cast<__half2*>(&kw0.x));
        float2 k23 = __half22float2(*reinterpret_cast<__half2*>(&kw0.y));
        float w0 = q01.x * k01.x + q01.y * k01.y + q23.x * k23.x + q23.y * k23.y;
        k01 = __half22float2(*reinterpret_cast<__half2*>(&kw1.x));
        k23 = __half22float2(*reinterpret_cast<__half2*>(&kw1.y));
        float w1 = q01.x * k01.x + q01.y * k01.y + q23.x * k23.x + q23.y * k23.y;

        #pragma unroll
        for (int s = 16; s; s >>= 1) {
            w0 += __shfl_xor_sync(0xffffffffu, w0, s);
            w1 += __shfl_xor_sync(0xffffffffu, w1, s);
        }
        w0 = (i0 > 0) ? w0 : 0.f;
        w1 = (i1 > 0) ? w1 : 0.f;

        // v = tanh(a + b): half2 adds, HW tanh.approx.f32, fp32 accumulate
        __half2 s0x = __hadd2(*reinterpret_cast<__half2*>(&aw0.x),
                              *reinterpret_cast<__half2*>(&bw0.x));
        __half2 s0y = __hadd2(*reinterpret_cast<__half2*>(&aw0.y),
                              *reinterpret_cast<__half2*>(&bw0.y));
        __half2 s1x = __hadd2(*reinterpret_cast<__half2*>(&aw1.x),
                              *reinterpret_cast<__half2*>(&bw1.x));
        __half2 s1y = __hadd2(*reinterpret_cast<__half2*>(&aw1.y),
                              *reinterpret_cast<__half2*>(&bw1.y));
        float2 f0x = __half22float2(s0x), f0y = __half22float2(s0y);
        float2 f1x = __half22float2(s1x), f1y = __half22float2(s1y);

        acc.x += w0 * tanha(f0x.x);
        acc.y += w0 * tanha(f0x.y);
        acc.z += w0 * tanha(f0y.x);
        acc.w += w0 * tanha(f0y.y);
        acc.x += w1 * tanha(f1x.x);
        acc.y += w1 * tanha(f1x.y);
        acc.z += w1 * tanha(f1y.x);
        acc.w += w1 * tanha(f1y.y);
    }
    *(float4*)(out + (size_t)gw * D + lane * 4) = acc;
}

extern "C" void kernel_launch(void* const* d_in, const int* in_sizes, int n_in,
                              void* d_out, int out_size)
{
    const float* item_table = (const float*)d_in[0];
    const float* opin_table = (const float*)d_in[1];
    const float* user_emb   = (const float*)d_in[2];
    const float* attr       = (const float*)d_in[3];
    const float* Wq         = (const float*)d_in[4];
    const float* bq         = (const float*)d_in[5];
    const float* Wk         = (const float*)d_in[6];
    const float* bk         = (const float*)d_in[7];
    const float* Wv         = (const float*)d_in[8];
    const float* bv         = (const float*)d_in[9];
    const int*   item_seqs  = (const int*)d_in[10];
    const int*   opin_seqs  = (const int*)d_in[11];
    float*       out        = (float*)d_out;

    const int n_item = in_sizes[0] / D;
    const int n_opi  = in_sizes[1] / D;
    const int U      = in_sizes[2] / D;
    const int L      = in_sizes[10] / U;

    __half *pK, *pA, *pB, *pQ;
    cudaGetSymbolAddress((void**)&pK, g_Ktab);
    cudaGetSymbolAddress((void**)&pA, g_A);
    cudaGetSymbolAddress((void**)&pB, g_B);
    cudaGetSymbolAddress((void**)&pQ, g_Q);

    const int nb_item = (n_item + 255) / 256;
    const int nb_opi  = (n_opi + 255) / 256;
    const int nb_user = (U + 255) / 256;

    const int smemB = 6 * TILE_B;   // 208896 B
    cudaFuncSetAttribute((const void*)tab_gemm_all,
                         cudaFuncAttributeMaxDynamicSharedMemorySize, smemB);

    setup_kernel<<<3, 256>>>(Wk, bk, Wv, bv, Wq, bq, attr);

    tab_gemm_all<<<nb_item + nb_opi + nb_user, 512, smemB>>>(
        item_table, opin_table, user_emb,
        pK, pA, pB, pQ, n_item, n_opi, U, nb_item, nb_opi);

    const int threads = 256;
    const int blocks  = (U * 32 + threads - 1) / threads;
    attend_kernel<<<blocks, threads>>>(item_seqs, opin_seqs, out, U, L);
}

// round 9
// speedup vs baseline: 3.4057x; 1.3278x over previous
#include <cuda_runtime.h>
#include <cuda_fp16.h>
#include <cstdint>

#define D    128
#define LDH  136                // half row stride in smem (8-half pad, conflict-free ldmatrix)
#define TILE_B (128 * LDH * 2)  // 34816 bytes per staged 128x128 fp16 tile

// fp16 scratch tables (allocation-free __device__ globals)
__device__ __half g_Ktab[50000 * D];   // tanh((attr + item) @ Wk^T + bk)
__device__ __half g_A   [50000 * D];   // item @ Wv^T
__device__ __half g_B   [ 5000 * D];   // opin @ Wv^T + bv
__device__ __half g_Q   [10000 * D];   // tanh(user @ Wq^T + bq)

// Preconverted weights (hi/lo fp16) + effective biases
__device__ __half g_Wh[3][128 * 128];  // 0: Wk, 1: Wv, 2: Wq
__device__ __half g_Wl[3][128 * 128];
__device__ float  g_eb[3][128];        // 0: bk + attr.Wk[n,:], 1: bv, 2: bq

static __device__ __forceinline__ uint32_t smem_u32(const void* p) {
    return (uint32_t)__cvta_generic_to_shared(p);
}
static __device__ __forceinline__ void ldsm_x4(uint32_t& r0, uint32_t& r1,
                                               uint32_t& r2, uint32_t& r3, uint32_t addr) {
    asm volatile("ldmatrix.sync.aligned.m8n8.x4.shared.b16 {%0,%1,%2,%3}, [%4];"
                 : "=r"(r0), "=r"(r1), "=r"(r2), "=r"(r3) : "r"(addr));
}
static __device__ __forceinline__ void mma16816(float* d,
                                                const uint32_t* a, const uint32_t* b) {
    asm volatile("mma.sync.aligned.m16n8k16.row.col.f32.f16.f16.f32 "
                 "{%0,%1,%2,%3}, {%4,%5,%6,%7}, {%8,%9}, {%0,%1,%2,%3};"
                 : "+f"(d[0]), "+f"(d[1]), "+f"(d[2]), "+f"(d[3])
                 : "r"(a[0]), "r"(a[1]), "r"(a[2]), "r"(a[3]), "r"(b[0]), "r"(b[1]));
}
static __device__ __forceinline__ float tanha(float x) {
    float y;
    asm("tanh.approx.f32 %0, %1;" : "=f"(y) : "f"(x));
    return y;
}

// ---------------- setup: preconvert W -> fp16 hi/lo, compute effective biases.
// grid = 51: blocks 0-47 convert W slices; 48-49 ebias j=0 (warp dot); 50 copies bv/bq.
__global__ void __launch_bounds__(256) setup_kernel(
    const float* __restrict__ Wk, const float* __restrict__ bk,
    const float* __restrict__ Wv, const float* __restrict__ bv,
    const float* __restrict__ Wq, const float* __restrict__ bq,
    const float* __restrict__ attr)
{
    const int b   = blockIdx.x;
    const int tid = threadIdx.x;

    if (b < 48) {
        const int j     = b >> 4;   // which W
        const int slice = b & 15;   // 1/16 of 16384 floats
        const float* W = (j == 0) ? Wk : (j == 1) ? Wv : Wq;
        const int e4 = (slice * 256 + tid) * 4;
        float4 v = *(const float4*)(W + e4);
        __half h0 = __float2half_rn(v.x), h1 = __float2half_rn(v.y);
        __half h2 = __float2half_rn(v.z), h3 = __float2half_rn(v.w);
        __half l0 = __float2half_rn(v.x - __half2float(h0));
        __half l1 = __float2half_rn(v.y - __half2float(h1));
        __half l2 = __float2half_rn(v.z - __half2float(h2));
        __half l3 = __float2half_rn(v.w - __half2float(h3));
        __half2 ph0 = __halves2half2(h0, h1), ph1 = __halves2half2(h2, h3);
        __half2 pl0 = __halves2half2(l0, l1), pl1 = __halves2half2(l2, l3);
        uint2 uh, ul;
        uh.x = *(uint32_t*)&ph0; uh.y = *(uint32_t*)&ph1;
        ul.x = *(uint32_t*)&pl0; ul.y = *(uint32_t*)&pl1;
        *(uint2*)(&g_Wh[j][e4]) = uh;
        *(uint2*)(&g_Wl[j][e4]) = ul;
    } else if (b < 50) {
        // ebias j=0: 64 rows per block, warp per 8 rows, float4 per lane
        const int wid = tid >> 5, lane = tid & 31;
        const float4 a4 = *(const float4*)(attr + lane * 4);
        #pragma unroll
        for (int t = 0; t < 8; t++) {
            const int n = (b - 48) * 64 + wid * 8 + t;
            float4 w4 = *(const float4*)(Wk + (size_t)n * D + lane * 4);
            float s = a4.x * w4.x + a4.y * w4.y + a4.z * w4.z + a4.w * w4.w;
            #pragma unroll
            for (int sh = 16; sh; sh >>= 1) s += __shfl_xor_sync(0xffffffffu, s, sh);
            if (lane == 0) g_eb[0][n] = s + __ldg(bk + n);
        }
    } else {
        if (tid < 128)      g_eb[1][tid]       = __ldg(bv + tid);
        else                g_eb[2][tid - 128] = __ldg(bq + tid - 128);
    }
}

// Stage a 128x128 fp32 tile as hi/lo fp16 into padded smem (512 threads).
static __device__ __forceinline__ void stage_hilo(__half* hi, __half* lo,
    const float* __restrict__ src, int row0, int M, int tid)
{
    #pragma unroll
    for (int idx = tid; idx < 128 * 32; idx += 512) {
        int r  = idx >> 5;
        int c4 = (idx & 31) << 2;
        int gr = row0 + r;
        float4 v = make_float4(0.f, 0.f, 0.f, 0.f);
        if (gr < M) v = *(const float4*)(src + (size_t)gr * D + c4);
        __half h0 = __float2half_rn(v.x), h1 = __float2half_rn(v.y);
        __half h2 = __float2half_rn(v.z), h3 = __float2half_rn(v.w);
        __half l0 = __float2half_rn(v.x - __half2float(h0));
        __half l1 = __float2half_rn(v.y - __half2float(h1));
        __half l2 = __float2half_rn(v.z - __half2float(h2));
        __half l3 = __float2half_rn(v.w - __half2float(h3));
        __half2 ph0 = __halves2half2(h0, h1), ph1 = __halves2half2(h2, h3);
        __half2 pl0 = __halves2half2(l0, l1), pl1 = __halves2half2(l2, l3);
        uint2 uh, ul;
        uh.x = *(uint32_t*)&ph0; uh.y = *(uint32_t*)&ph1;
        ul.x = *(uint32_t*)&pl0; ul.y = *(uint32_t*)&pl1;
        *(uint2*)(hi + r * LDH + c4) = uh;
        *(uint2*)(lo + r * LDH + c4) = ul;
    }
}

// Copy a preconverted 128x128 fp16 tile into padded smem.
static __device__ __forceinline__ void stage_w(__half* dst, const __half* __restrict__ src,
                                               int tid)
{
    #pragma unroll
    for (int idx = tid; idx < 128 * 16; idx += 512) {
        int r = idx >> 4;
        int c = (idx & 15) << 3;
        *(uint4*)(dst + r * LDH + c) = *(const uint4*)(src + r * 128 + c);
    }
}

// All three table GEMMs in ONE launch; 256 rows per CTA (two 128-row sub-tiles).
__global__ void __launch_bounds__(512) tab_gemm_all(
    const float* __restrict__ item_table, const float* __restrict__ opin_table,
    const float* __restrict__ user_emb,
    __half* __restrict__ pK, __half* __restrict__ pA,
    __half* __restrict__ pB, __half* __restrict__ pQ,
    int n_item, int n_opi, int n_user, int nb_item, int nb_opi)
{
    extern __shared__ char smc[];
    __half* Xhi = (__half*)smc;
    __half* Xlo = (__half*)(smc + TILE_B);
    __half* Wsm = (__half*)(smc + 2 * TILE_B);   // up to 2 (hi,lo) W tile pairs

    const int tid  = threadIdx.x;
    const int lane = tid & 31;
    const int wid  = tid >> 5;
    const int wm   = wid >> 2;
    const int wn   = wid & 3;

    // role selection
    const int bid = blockIdx.x;
    const float* X;
    __half *out0, *out1 = nullptr;
    int M, rbase, jw0, jw1 = -1;
    bool two = false, tanh0;
    if (bid < nb_item) {
        X = item_table; out0 = pK; out1 = pA; M = n_item;
        rbase = bid * 256; jw0 = 0; jw1 = 1; two = true; tanh0 = true;
    } else if (bid < nb_item + nb_opi) {
        X = opin_table; out0 = pB; M = n_opi;
        rbase = (bid - nb_item) * 256; jw0 = 1; tanh0 = false;
    } else {
        X = user_emb; out0 = pQ; M = n_user;
        rbase = (bid - nb_item - nb_opi) * 256; jw0 = 2; tanh0 = true;
    }

    // stage W tiles (from preconverted fp16 globals)
    stage_w(Wsm,               g_Wh[jw0], tid);
    stage_w(Wsm + 128 * LDH,   g_Wl[jw0], tid);
    if (two) {
        stage_w(Wsm + 2 * 128 * LDH, g_Wh[jw1], tid);
        stage_w(Wsm + 3 * 128 * LDH, g_Wl[jw1], tid);
    }

    // ldmatrix lane-address mapping
    const int ag   = lane >> 3;
    const int arow = wm * 32 + (ag & 1) * 8 + (lane & 7);
    const int acol = (ag >> 1) * 8;
    const uint32_t aHi = smem_u32(Xhi + arow * LDH + acol);
    const uint32_t aLo = smem_u32(Xlo + arow * LDH + acol);
    const int brow = wn * 32 + (ag >> 1) * 8 + (lane & 7);
    const int bcol = (ag & 1) * 8;
    const uint32_t bOff = (uint32_t)(brow * LDH + bcol) * 2;
    const uint32_t bHi0 = smem_u32(Wsm) + bOff;
    const uint32_t bHi1 = smem_u32(Wsm + 2 * 128 * LDH) + bOff;

    #pragma unroll 1
    for (int sub = 0; sub < 2; sub++) {
        const int row0 = rbase + sub * 128;
        if (row0 >= M) break;

        stage_hilo(Xhi, Xlo, X, row0, M, tid);
        __syncthreads();

        float acc[2][2][4][4];   // [j][mf][nf][c]
        #pragma unroll
        for (int j = 0; j < 2; j++)
            #pragma unroll
            for (int mf = 0; mf < 2; mf++)
                #pragma unroll
                for (int nf = 0; nf < 4; nf++)
                    #pragma unroll
                    for (int c = 0; c < 4; c++) acc[j][mf][nf][c] = 0.f;

        #pragma unroll
        for (int ks = 0; ks < 8; ks++) {
            const uint32_t ko = (uint32_t)ks * 32;
            uint32_t ahi[2][4], alo[2][4];
            #pragma unroll
            for (int mf = 0; mf < 2; mf++) {
                const uint32_t mo = (uint32_t)(mf * 16 * LDH) * 2;
                ldsm_x4(ahi[mf][0], ahi[mf][1], ahi[mf][2], ahi[mf][3], aHi + mo + ko);
                ldsm_x4(alo[mf][0], alo[mf][1], alo[mf][2], alo[mf][3], aLo + mo + ko);
            }
            {   // j = 0
                uint32_t bhi[4][2], blo[4][2];
                #pragma unroll
                for (int nh = 0; nh < 2; nh++) {
                    const uint32_t no = (uint32_t)(nh * 16 * LDH) * 2;
                    ldsm_x4(bhi[nh*2][0], bhi[nh*2][1], bhi[nh*2+1][0], bhi[nh*2+1][1],
                            bHi0 + no + ko);
                    ldsm_x4(blo[nh*2][0], blo[nh*2][1], blo[nh*2+1][0], blo[nh*2+1][1],
                            bHi0 + (uint32_t)TILE_B + no + ko);
                }
                #pragma unroll
                for (int mf = 0; mf < 2; mf++)
                    #pragma unroll
                    for (int nf = 0; nf < 4; nf++) {
                        mma16816(acc[0][mf][nf], ahi[mf], bhi[nf]);
                        mma16816(acc[0][mf][nf], ahi[mf], blo[nf]);
                        mma16816(acc[0][mf][nf], alo[mf], bhi[nf]);
                    }
            }
            if (two) {   // j = 1
                uint32_t bhi[4][2], blo[4][2];
                #pragma unroll
                for (int nh = 0; nh < 2; nh++) {
                    const uint32_t no = (uint32_t)(nh * 16 * LDH) * 2;
                    ldsm_x4(bhi[nh*2][0], bhi[nh*2][1], bhi[nh*2+1][0], bhi[nh*2+1][1],
                            bHi1 + no + ko);
                    ldsm_x4(blo[nh*2][0], blo[nh*2][1], blo[nh*2+1][0], blo[nh*2+1][1],
                            bHi1 + (uint32_t)TILE_B + no + ko);
                }
                #pragma unroll
                for (int mf = 0; mf < 2; mf++)
                    #pragma unroll
                    for (int nf = 0; nf < 4; nf++) {
                        mma16816(acc[1][mf][nf], ahi[mf], bhi[nf]);
                        mma16816(acc[1][mf][nf], ahi[mf], blo[nf]);
                        mma16816(acc[1][mf][nf], alo[mf], bhi[nf]);
                    }
            }
        }
        __syncthreads();   // all ldsm done; Xhi/Xlo free for next sub-tile

        // epilogue (tanh.approx: attend-side swap moved rel_err only 3.40->3.87e-4)
        const int NW = two ? 2 : 1;
        for (int j = 0; j < NW; j++) {
            __half* outp = (j == 0) ? out0 : out1;
            const bool T = (j == 0) ? tanh0 : false;
            const bool hasb = (j == 0);
            const float* ebj = g_eb[(j == 0) ? jw0 : jw1];
            #pragma unroll
            for (int mf = 0; mf < 2; mf++) {
                const int r0 = row0 + wm * 32 + mf * 16 + (lane >> 2);
                const int r1 = r0 + 8;
                #pragma unroll
                for (int nf = 0; nf < 4; nf++) {
                    const int col = wn * 32 + nf * 8 + 2 * (lane & 3);
                    float e0 = hasb ? __ldg(ebj + col)     : 0.f;
                    float e1 = hasb ? __ldg(ebj + col + 1) : 0.f;
                    float v0 = acc[j][mf][nf][0] + e0, v1 = acc[j][mf][nf][1] + e1;
                    float v2 = acc[j][mf][nf][2] + e0, v3 = acc[j][mf][nf][3] + e1;
                    if (T) { v0 = tanha(v0); v1 = tanha(v1); v2 = tanha(v2); v3 = tanha(v3); }
                    if (r0 < M) *(__half2*)(outp + (size_t)r0 * D + col) = __floats2half2_rn(v0, v1);
                    if (r1 < M) *(__half2*)(outp + (size_t)r1 * D + col) = __floats2half2_rn(v2, v3);
                }
            }
        }
    }
}

// One warp per user; 4-step pipelined (12 outstanding gathers), int2 index loads.
__global__ void __launch_bounds__(256) attend_kernel(
    const int* __restrict__ item_seqs,
    const int* __restrict__ opin_seqs,
    float* __restrict__ out, int U, int L)
{
    const int gw   = (int)((blockIdx.x * blockDim.x + threadIdx.x) >> 5);
    const int lane = threadIdx.x & 31;
    if (gw >= U) return;

    const uint2* Kt = (const uint2*)g_Ktab;   // 32 uint2 per row
    const uint2* At = (const uint2*)g_A;
    const uint2* Bt = (const uint2*)g_B;

    uint2 qw = *((const uint2*)g_Q + (size_t)gw * 32 + lane);
    float2 q01 = __half22float2(*reinterpret_cast<__half2*>(&qw.x));
    float2 q23 = __half22float2(*reinterpret_cast<__half2*>(&qw.y));

    float4 acc = make_float4(0.f, 0.f, 0.f, 0.f);
    const int* is = item_seqs + (size_t)gw * L;
    const int* os = opin_seqs + (size_t)gw * L;

    const int Lm = L & ~3;
    for (int l = 0; l < Lm; l += 4) {
        int2 i01 = __ldg((const int2*)(is + l));
        int2 i23 = __ldg((const int2*)(is + l + 2));
        int2 o01 = __ldg((const int2*)(os + l));
        int2 o23 = __ldg((const int2*)(os + l + 2));
        int ii[4] = {i01.x, i01.y, i23.x, i23.y};
        int oo[4] = {o01.x, o01.y, o23.x, o23.y};

        uint2 kw[4], aw[4], bw[4];
        #pragma unroll
        for (int t = 0; t < 4; t++) {
            kw[t] = __ldg(Kt + (size_t)ii[t] * 32 + lane);
            aw[t] = __ldg(At + (size_t)ii[t] * 32 + lane);
            bw[t] = __ldg(Bt + (size_t)oo[t] * 32 + lane);
        }

        float w[4];
        #pragma unroll
        for (int t = 0; t < 4; t++) {
            float2 k01 = __half22float2(*reinterpret_cast<__half2*>(&kw[t].x));
            float2 k23 = __half22float2(*reinterpret_cast<__half2*>(&kw[t].y));
            w[t] = q01.x * k01.x + q01.y * k01.y + q23.x * k23.x + q23.y * k23.y;
        }
        #pragma unroll
        for (int s = 16; s; s >>= 1) {
            w[0] += __shfl_xor_sync(0xffffffffu, w[0], s);
            w[1] += __shfl_xor_sync(0xffffffffu, w[1], s);
            w[2] += __shfl_xor_sync(0xffffffffu, w[2], s);
            w[3] += __shfl_xor_sync(0xffffffffu, w[3], s);
        }
        #pragma unroll
        for (int t = 0; t < 4; t++) {
            float wt = (ii[t] > 0) ? w[t] : 0.f;
            __half2 sx = __hadd2(*reinterpret_cast<__half2*>(&aw[t].x),
                                 *reinterpret_cast<__half2*>(&bw[t].x));
            __half2 sy = __hadd2(*reinterpret_cast<__half2*>(&aw[t].y),
                                 *reinterpret_cast<__half2*>(&bw[t].y));
            float2 fx = __half22float2(sx), fy = __half22float2(sy);
            acc.x += wt * tanha(fx.x);
            acc.y += wt * tanha(fx.y);
            acc.z += wt * tanha(fy.x);
            acc.w += wt * tanha(fy.y);
        }
    }
    for (int l = Lm; l < L; ++l) {
        int i = __ldg(is + l);
        int o = __ldg(os + l);
        uint2 kw = __ldg(Kt + (size_t)i * 32 + lane);
        uint2 aw = __ldg(At + (size_t)i * 32 + lane);
        uint2 bw = __ldg(Bt + (size_t)o * 32 + lane);
        float2 k01 = __half22float2(*reinterpret_cast<__half2*>(&kw.x));
        float2 k23 = __half22float2(*reinterpret_cast<__half2*>(&kw.y));
        float w = q01.x * k01.x + q01.y * k01.y + q23.x * k23.x + q23.y * k23.y;
        #pragma unroll
        for (int s = 16; s; s >>= 1) w += __shfl_xor_sync(0xffffffffu, w, s);
        w = (i > 0) ? w : 0.f;
        __half2 sx = __hadd2(*reinterpret_cast<__half2*>(&aw.x),
                             *reinterpret_cast<__half2*>(&bw.x));
        __half2 sy = __hadd2(*reinterpret_cast<__half2*>(&aw.y),
                             *reinterpret_cast<__half2*>(&bw.y));
        float2 fx = __half22float2(sx), fy = __half22float2(sy);
        acc.x += w * tanha(fx.x);
        acc.y += w * tanha(fx.y);
        acc.z += w * tanha(fy.x);
        acc.w += w * tanha(fy.y);
    }
    *(float4*)(out + (size_t)gw * D + lane * 4) = acc;
}

extern "C" void kernel_launch(void* const* d_in, const int* in_sizes, int n_in,
                              void* d_out, int out_size)
{
    const float* item_table = (const float*)d_in[0];
    const float* opin_table = (const float*)d_in[1];
    const float* user_emb   = (const float*)d_in[2];
    const float* attr       = (const float*)d_in[3];
    const float* Wq         = (const float*)d_in[4];
    const float* bq         = (const float*)d_in[5];
    const float* Wk         = (const float*)d_in[6];
    const float* bk         = (const float*)d_in[7];
    const float* Wv         = (const float*)d_in[8];
    const float* bv         = (const float*)d_in[9];
    const int*   item_seqs  = (const int*)d_in[10];
    const int*   opin_seqs  = (const int*)d_in[11];
    float*       out        = (float*)d_out;

    const int n_item = in_sizes[0] / D;
    const int n_opi  = in_sizes[1] / D;
    const int U      = in_sizes[2] / D;
    const int L      = in_sizes[10] / U;

    __half *pK, *pA, *pB, *pQ;
    cudaGetSymbolAddress((void**)&pK, g_Ktab);
    cudaGetSymbolAddress((void**)&pA, g_A);
    cudaGetSymbolAddress((void**)&pB, g_B);
    cudaGetSymbolAddress((void**)&pQ, g_Q);

    const int nb_item = (n_item + 255) / 256;
    const int nb_opi  = (n_opi + 255) / 256;
    const int nb_user = (U + 255) / 256;

    const int smemB = 6 * TILE_B;   // 208896 B
    cudaFuncSetAttribute((const void*)tab_gemm_all,
                         cudaFuncAttributeMaxDynamicSharedMemorySize, smemB);

    setup_kernel<<<51, 256>>>(Wk, bk, Wv, bv, Wq, bq, attr);

    tab_gemm_all<<<nb_item + nb_opi + nb_user, 512, smemB>>>(
        item_table, opin_table, user_emb,
        pK, pA, pB, pQ, n_item, n_opi, U, nb_item, nb_opi);

    const int threads = 256;
    const int blocks  = (U * 32 + threads - 1) / threads;
    attend_kernel<<<blocks, threads>>>(item_seqs, opin_seqs, out, U, L);
}